// round 6
// baseline (speedup 1.0000x reference)
#include <cuda_runtime.h>

#define IMG_H 512
#define IMG_W 512
#define HW (IMG_H * IMG_W)
#define TILE_W 64
#define TILE_H 32
#define XC 4            // x lattice corners covered by a tile (span<=2 -> 4)
#define YC 3            // y lattice corners covered by a tile (span<=1 -> 3)
#define NCOR (XC * YC)  // 12
#define ZS 8
#define CPAD 36         // channel pad: z-stride 36 words == 4 mod 32 -> distinct banks per z
#define ZSTR CPAD
#define CORSTR (ZS * CPAD)   // 288 words, == 0 mod 32

// Fused bilateral-grid pipeline, smem-staged grid tiles.
// Block = 64x32 pixel tile, 256 threads, 8 pixels/thread (one column each).
__global__ __launch_bounds__(256, 4) void bgrid_fused_tile(
    const float* __restrict__ src,    // (8,3,512,512)
    const float* __restrict__ grid1,  // (8,32,8,16,16)
    const float* __restrict__ grid2,  // (8,27,8,16,16)
    const float* __restrict__ w1, const float* __restrict__ b1,
    const float* __restrict__ w2, const float* __restrict__ b2,
    const float* __restrict__ w3, const float* __restrict__ b3,
    const float* __restrict__ w4, const float* __restrict__ b4,
    float* __restrict__ out)          // (8,3,512,512)
{
    __shared__ float s1[NCOR * ZS * CPAD];   // 13824 B
    __shared__ float s2[NCOR * ZS * CPAD];   // 13824 B
    __shared__ float sw1[48], sb1[16], sw2[16], sw3[128], sb3[16], sw4[16];
    __shared__ float sb2s, sb4s;

    const int tid = threadIdx.x;
    const int b = blockIdx.z;
    const int X = blockIdx.x * TILE_W;
    const int Y = blockIdx.y * TILE_H;

    // lattice cell range of this tile (exact: fx = px*15/512, px*15 < 2^13)
    const int x0min = (X * 15) >> 9;
    const int y0min = (Y * 15) >> 9;

    // ---- stage weights ----
    if (tid < 48)  sw1[tid] = w1[tid];
    if (tid < 16) {
        sb1[tid] = b1[tid];
        sw2[tid] = w2[tid];
        sb3[tid] = b3[tid];
        sw4[tid] = w4[tid];
    }
    if (tid < 128) sw3[tid] = w3[tid];
    if (tid == 0) { sb2s = b2[0]; sb4s = b4[0]; }

    // ---- stage grid tiles (footprint: 12 xy-corners x 8 z x C channels) ----
    {
        const float* g1b = grid1 + b * (32 * 2048);
        for (int i = tid; i < NCOR * ZS * 32; i += 256) {   // 3072
            const int c = i / (NCOR * ZS);                  // 0..31
            const int rem = i - c * (NCOR * ZS);
            const int z = rem / NCOR;
            const int xy = rem - z * NCOR;
            const int yi = xy >> 2;
            const int xi = xy & 3;
            const int y = min(y0min + yi, 15);
            const int x = min(x0min + xi, 15);
            s1[xy * CORSTR + z * ZSTR + c] = g1b[c * 2048 + z * 256 + y * 16 + x];
        }
        const float* g2b = grid2 + b * (27 * 2048);
        for (int i = tid; i < NCOR * ZS * 28; i += 256) {   // 2688
            const int c = i / (NCOR * ZS);                  // 0..27
            const int rem = i - c * (NCOR * ZS);
            const int z = rem / NCOR;
            const int xy = rem - z * NCOR;
            const int yi = xy >> 2;
            const int xi = xy & 3;
            const int y = min(y0min + yi, 15);
            const int x = min(x0min + xi, 15);
            s2[xy * CORSTR + z * ZSTR + c] =
                (c < 27) ? g2b[c * 2048 + z * 256 + y * 16 + x] : 0.0f;
        }
    }
    __syncthreads();

    // ---- per-thread column ----
    const int tx = tid & 63;
    const int ty = tid >> 6;                 // 0..3
    const int px = X + tx;
    const float fx = (float)px * (15.0f / 512.0f);
    const int x0 = (int)fx;
    const float wxv = fx - (float)x0;
    const int xg = x0 - x0min;               // 0..2
    const float wxa[2] = {1.0f - wxv, wxv};

    const float* srcb = src + (b * 3) * HW;
    float* outb = out + (b * 3) * HW;

#pragma unroll 2
    for (int p = 0; p < 8; p++) {
        const int py = Y + ty + p * 4;
        const float fy = (float)py * (15.0f / 512.0f);
        const int y0 = (int)fy;
        const float wyv = fy - (float)y0;
        const int yg = y0 - y0min;           // 0..1
        const float wya[2] = {1.0f - wyv, wyv};

        // corner smem bases (shared geometry for s1 and s2)
        int cb[2][2];
#pragma unroll
        for (int yi = 0; yi < 2; yi++)
#pragma unroll
            for (int xi = 0; xi < 2; xi++)
                cb[yi][xi] = ((yg + yi) * XC + (xg + xi)) * CORSTR;

        // ---- src pixel ----
        const int pix = py * IMG_W + px;
        const float s0 = srcb[pix];
        const float s1v_ = srcb[HW + pix];
        const float s2v_ = srcb[2 * HW + pix];

        // ---- guide NN #1 ----
        float g = sb2s;
#pragma unroll
        for (int o = 0; o < 16; o++) {
            float t = sb1[o];
            t = fmaf(sw1[o * 3 + 0], s0, t);
            t = fmaf(sw1[o * 3 + 1], s1v_, t);
            t = fmaf(sw1[o * 3 + 2], s2v_, t);
            t = fmaxf(t, 0.0f);
            g = fmaf(sw2[o], t, g);
        }
        g = tanhf(g);

        // ---- z for slice 1 ----
        float fz = fminf(fmaxf((g + 1.0f) * 3.5f, 0.0f), 7.0f);
        int z0 = (int)fz;
        if (z0 > 7) z0 = 7;
        int z1 = min(z0 + 1, 7);
        float wz = fz - (float)z0;

        // ---- slice grid1 from smem, fold into hid[8] ----
        float hid[8];
#pragma unroll
        for (int k = 0; k < 8; k++) hid[k] = 0.0f;
        {
            const float wza[2] = {1.0f - wz, wz};
            const int zoff[2] = {z0 * ZSTR, z1 * ZSTR};
#pragma unroll
            for (int zi = 0; zi < 2; zi++) {
#pragma unroll
                for (int yi = 0; yi < 2; yi++) {
#pragma unroll
                    for (int xi = 0; xi < 2; xi++) {
                        const float wc = wza[zi] * wya[yi] * wxa[xi];
                        const float* ptr = s1 + cb[yi][xi] + zoff[zi];
                        const float ws[4] = {wc * s0, wc * s1v_, wc * s2v_, wc};
#pragma unroll
                        for (int j = 0; j < 8; j++) {
                            const float4 v = *(const float4*)(ptr + 4 * j);
                            const float m = ws[j >> 1];
                            const int k = (j & 1) * 4;
                            hid[k + 0] = fmaf(v.x, m, hid[k + 0]);
                            hid[k + 1] = fmaf(v.y, m, hid[k + 1]);
                            hid[k + 2] = fmaf(v.z, m, hid[k + 2]);
                            hid[k + 3] = fmaf(v.w, m, hid[k + 3]);
                        }
                    }
                }
            }
        }
#pragma unroll
        for (int k = 0; k < 8; k++) hid[k] = fmaxf(hid[k], 0.0f);

        // ---- guide NN #2 ----
        float g2acc = sb4s;
#pragma unroll
        for (int o = 0; o < 16; o++) {
            float t = sb3[o];
#pragma unroll
            for (int q = 0; q < 8; q++) t = fmaf(sw3[o * 8 + q], hid[q], t);
            t = fmaxf(t, 0.0f);
            g2acc = fmaf(sw4[o], t, g2acc);
        }
        g2acc = tanhf(g2acc);

        // ---- z for slice 2 ----
        fz = fminf(fmaxf((g2acc + 1.0f) * 3.5f, 0.0f), 7.0f);
        z0 = (int)fz;
        if (z0 > 7) z0 = 7;
        z1 = min(z0 + 1, 7);
        wz = fz - (float)z0;

        // ---- slice grid2 from smem, fold into out[3] ----
        float r[3] = {0.0f, 0.0f, 0.0f};
        {
            float m2[10];
#pragma unroll
            for (int q = 0; q < 8; q++) m2[q] = hid[q];
            m2[8] = 1.0f;
            m2[9] = 0.0f;

            const float wza[2] = {1.0f - wz, wz};
            const int zoff[2] = {z0 * ZSTR, z1 * ZSTR};
#pragma unroll
            for (int zi = 0; zi < 2; zi++) {
#pragma unroll
                for (int yi = 0; yi < 2; yi++) {
#pragma unroll
                    for (int xi = 0; xi < 2; xi++) {
                        const float wc = wza[zi] * wya[yi] * wxa[xi];
                        const float* ptr = s2 + cb[yi][xi] + zoff[zi];
                        float wm[10];
#pragma unroll
                        for (int q = 0; q < 10; q++) wm[q] = wc * m2[q];
#pragma unroll
                        for (int j = 0; j < 7; j++) {
                            const float4 v = *(const float4*)(ptr + 4 * j);
                            const int c0 = 4 * j;
                            r[(c0 + 0) % 3] = fmaf(v.x, wm[(c0 + 0) / 3], r[(c0 + 0) % 3]);
                            r[(c0 + 1) % 3] = fmaf(v.y, wm[(c0 + 1) / 3], r[(c0 + 1) % 3]);
                            r[(c0 + 2) % 3] = fmaf(v.z, wm[(c0 + 2) / 3], r[(c0 + 2) % 3]);
                            r[(c0 + 3) % 3] = fmaf(v.w, wm[(c0 + 3) / 3], r[(c0 + 3) % 3]);
                        }
                    }
                }
            }
        }

        outb[pix]          = r[0];
        outb[HW + pix]     = r[1];
        outb[2 * HW + pix] = r[2];
    }
}

extern "C" void kernel_launch(void* const* d_in, const int* in_sizes, int n_in,
                              void* d_out, int out_size) {
    const float* src   = (const float*)d_in[0];
    const float* grid1 = (const float*)d_in[1];
    const float* grid2 = (const float*)d_in[2];
    const float* w1    = (const float*)d_in[3];
    const float* b1    = (const float*)d_in[4];
    const float* w2    = (const float*)d_in[5];
    const float* b2    = (const float*)d_in[6];
    const float* w3    = (const float*)d_in[7];
    const float* b3    = (const float*)d_in[8];
    const float* w4    = (const float*)d_in[9];
    const float* b4    = (const float*)d_in[10];
    float* out = (float*)d_out;

    dim3 grid(IMG_W / TILE_W, IMG_H / TILE_H, 8);   // 8 x 16 x 8 = 1024 blocks
    bgrid_fused_tile<<<grid, 256>>>(src, grid1, grid2,
                                    w1, b1, w2, b2, w3, b3, w4, b4, out);
}

// round 7
// speedup vs baseline: 2.0000x; 2.0000x over previous
#include <cuda_runtime.h>
#include <cuda_fp16.h>

#define IMG_H 512
#define IMG_W 512
#define HW (IMG_H * IMG_W)

// Channel-last fp16 staging: [b][z][y][x][32]  (1 MB each)
__device__ __half g1h[8 * 8 * 16 * 16 * 32];
__device__ __half g2h[8 * 8 * 16 * 16 * 32];   // 27 real channels + 5 zero pad

__global__ __launch_bounds__(256) void transpose_grids_h(
    const float* __restrict__ g1, const float* __restrict__ g2)
{
    const int i = blockIdx.x * 256 + threadIdx.x;
    // grid1: [b][32][8][16][16] -> [b][z][y][x][32]
    if (i < 8 * 32 * 8 * 256) {
        const int x = i & 15, y = (i >> 4) & 15, z = (i >> 8) & 7;
        const int c = (i >> 11) & 31, b = i >> 16;
        g1h[(((b * 8 + z) * 16 + y) * 16 + x) * 32 + c] = __float2half(g1[i]);
    }
    // grid2: [b][27][8][16][16] -> [b][z][y][x][32] (c<27)
    if (i < 8 * 27 * 8 * 256) {
        const int x = i & 15, y = (i >> 4) & 15, z = (i >> 8) & 7;
        const int t = i >> 11;
        const int c = t % 27, b = t / 27;
        g2h[(((b * 8 + z) * 16 + y) * 16 + x) * 32 + c] = __float2half(g2[i]);
    }
    // zero pad channels 27..31
    if (i < 8 * 8 * 256) {
#pragma unroll
        for (int c = 27; c < 32; c++) g2h[i * 32 + c] = __float2half(0.0f);
    }
}

__device__ __forceinline__ float tanh_approx(float x) {
    float y;
    asm("tanh.approx.f32 %0, %1;" : "=f"(y) : "f"(x));
    return y;
}

__global__ __launch_bounds__(256, 4) void bgrid_fused_kernel(
    const float* __restrict__ src,    // (8,3,512,512)
    const float* __restrict__ w1, const float* __restrict__ b1,
    const float* __restrict__ w2, const float* __restrict__ b2,
    const float* __restrict__ w3, const float* __restrict__ b3,
    const float* __restrict__ w4, const float* __restrict__ b4,
    float* __restrict__ out)          // (8,3,512,512)
{
    __shared__ float sw1[48], sb1[16], sw2[16], sw3[128], sb3[16], sw4[16];
    __shared__ float sb2s, sb4s;

    const int tid = threadIdx.x;
    if (tid < 48)  sw1[tid] = w1[tid];
    if (tid < 16) {
        sb1[tid] = b1[tid];
        sw2[tid] = w2[tid];
        sb3[tid] = b3[tid];
        sw4[tid] = w4[tid];
    }
    if (tid < 128) sw3[tid] = w3[tid];
    if (tid == 0) { sb2s = b2[0]; sb4s = b4[0]; }
    __syncthreads();

    const int idx = blockIdx.x * 256 + tid;
    const int px = idx & 511;
    const int py = (idx >> 9) & 511;
    const int pb = idx >> 18;

    // ---- src pixel ----
    const float* srcp = src + (pb * 3) * HW + py * IMG_W + px;
    const float s0 = srcp[0];
    const float s1 = srcp[HW];
    const float s2 = srcp[2 * HW];

    // ---- guide NN #1 ----
    float g = sb2s;
#pragma unroll
    for (int o = 0; o < 16; o++) {
        float t = sb1[o];
        t = fmaf(sw1[o * 3 + 0], s0, t);
        t = fmaf(sw1[o * 3 + 1], s1, t);
        t = fmaf(sw1[o * 3 + 2], s2, t);
        t = fmaxf(t, 0.0f);
        g = fmaf(sw2[o], t, g);
    }
    g = tanh_approx(g);

    // ---- xy lattice (fx in [0,14.97], x0+1 <= 15 always) ----
    const float fx = (float)px * (15.0f / 512.0f);
    const float fy = (float)py * (15.0f / 512.0f);
    const int x0 = (int)fx;
    const int y0 = (int)fy;
    const float wx = fx - (float)x0;
    const float wy = fy - (float)y0;
    const float wya[2] = {1.0f - wy, wy};
    const float wxa[2] = {1.0f - wx, wx};
    const int oxy[2][2] = {{y0 * 16 + x0,      y0 * 16 + x0 + 1},
                           {y0 * 16 + x0 + 16, y0 * 16 + x0 + 17}};

    // ---- z for slice 1 ----
    float fz = fminf(fmaxf((g + 1.0f) * 3.5f, 0.0f), 7.0f);
    int z0 = (int)fz;
    if (z0 > 7) z0 = 7;
    int z1 = min(z0 + 1, 7);
    float wz = fz - (float)z0;

    // ---- slice grid1 (fp16 channel-last, 4 x uint4 per corner) -> hid[8] ----
    float hid[8];
#pragma unroll
    for (int k = 0; k < 8; k++) hid[k] = 0.0f;
    {
        const float wza[2] = {1.0f - wz, wz};
        const int   za[2]  = {z0, z1};
#pragma unroll
        for (int zi = 0; zi < 2; zi++) {
            const int czb = (pb * 8 + za[zi]) * 256;
#pragma unroll
            for (int yi = 0; yi < 2; yi++) {
#pragma unroll
                for (int xi = 0; xi < 2; xi++) {
                    const float wc = wza[zi] * wya[yi] * wxa[xi];
                    const uint4* p = (const uint4*)(g1h + (czb + oxy[yi][xi]) * 32);
                    const float ws[4] = {wc * s0, wc * s1, wc * s2, wc};
#pragma unroll
                    for (int j = 0; j < 4; j++) {   // 8 channels per uint4, a = j
                        const uint4 v = __ldg(p + j);
                        const float m = ws[j];
                        float2 f;
                        f = __half22float2(*(const __half2*)&v.x);
                        hid[0] = fmaf(f.x, m, hid[0]);
                        hid[1] = fmaf(f.y, m, hid[1]);
                        f = __half22float2(*(const __half2*)&v.y);
                        hid[2] = fmaf(f.x, m, hid[2]);
                        hid[3] = fmaf(f.y, m, hid[3]);
                        f = __half22float2(*(const __half2*)&v.z);
                        hid[4] = fmaf(f.x, m, hid[4]);
                        hid[5] = fmaf(f.y, m, hid[5]);
                        f = __half22float2(*(const __half2*)&v.w);
                        hid[6] = fmaf(f.x, m, hid[6]);
                        hid[7] = fmaf(f.y, m, hid[7]);
                    }
                }
            }
        }
    }
#pragma unroll
    for (int k = 0; k < 8; k++) hid[k] = fmaxf(hid[k], 0.0f);

    // ---- guide NN #2 ----
    float g2acc = sb4s;
#pragma unroll
    for (int o = 0; o < 16; o++) {
        float t = sb3[o];
#pragma unroll
        for (int q = 0; q < 8; q++) t = fmaf(sw3[o * 8 + q], hid[q], t);
        t = fmaxf(t, 0.0f);
        g2acc = fmaf(sw4[o], t, g2acc);
    }
    g2acc = tanh_approx(g2acc);

    // ---- z for slice 2 ----
    fz = fminf(fmaxf((g2acc + 1.0f) * 3.5f, 0.0f), 7.0f);
    z0 = (int)fz;
    if (z0 > 7) z0 = 7;
    z1 = min(z0 + 1, 7);
    wz = fz - (float)z0;

    // ---- slice grid2 (fp16, 4 x uint4 per corner) -> out[3] ----
    // channel c: q = c%3, p = c/3 (p==8 bias; c>=27 are zero-padded)
    float r[3] = {0.0f, 0.0f, 0.0f};
    {
        float m2[11];
#pragma unroll
        for (int q = 0; q < 8; q++) m2[q] = hid[q];
        m2[8] = 1.0f; m2[9] = 0.0f; m2[10] = 0.0f;

        const float wza[2] = {1.0f - wz, wz};
        const int   za[2]  = {z0, z1};
#pragma unroll
        for (int zi = 0; zi < 2; zi++) {
            const int czb = (pb * 8 + za[zi]) * 256;
#pragma unroll
            for (int yi = 0; yi < 2; yi++) {
#pragma unroll
                for (int xi = 0; xi < 2; xi++) {
                    const float wc = wza[zi] * wya[yi] * wxa[xi];
                    const uint4* p = (const uint4*)(g2h + (czb + oxy[yi][xi]) * 32);
                    float wm[11];
#pragma unroll
                    for (int q = 0; q < 9; q++) wm[q] = wc * m2[q];
                    wm[9] = 0.0f; wm[10] = 0.0f;
#pragma unroll
                    for (int j = 0; j < 4; j++) {
                        const uint4 v = __ldg(p + j);
                        const int c0 = 8 * j;
                        float2 f;
                        f = __half22float2(*(const __half2*)&v.x);
                        r[(c0 + 0) % 3] = fmaf(f.x, wm[(c0 + 0) / 3], r[(c0 + 0) % 3]);
                        r[(c0 + 1) % 3] = fmaf(f.y, wm[(c0 + 1) / 3], r[(c0 + 1) % 3]);
                        f = __half22float2(*(const __half2*)&v.y);
                        r[(c0 + 2) % 3] = fmaf(f.x, wm[(c0 + 2) / 3], r[(c0 + 2) % 3]);
                        r[(c0 + 3) % 3] = fmaf(f.y, wm[(c0 + 3) / 3], r[(c0 + 3) % 3]);
                        f = __half22float2(*(const __half2*)&v.z);
                        r[(c0 + 4) % 3] = fmaf(f.x, wm[(c0 + 4) / 3], r[(c0 + 4) % 3]);
                        r[(c0 + 5) % 3] = fmaf(f.y, wm[(c0 + 5) / 3], r[(c0 + 5) % 3]);
                        f = __half22float2(*(const __half2*)&v.w);
                        r[(c0 + 6) % 3] = fmaf(f.x, wm[(c0 + 6) / 3], r[(c0 + 6) % 3]);
                        r[(c0 + 7) % 3] = fmaf(f.y, wm[(c0 + 7) / 3], r[(c0 + 7) % 3]);
                    }
                }
            }
        }
    }

    float* outp = out + (pb * 3) * HW + py * IMG_W + px;
    outp[0]      = r[0];
    outp[HW]     = r[1];
    outp[2 * HW] = r[2];
}

extern "C" void kernel_launch(void* const* d_in, const int* in_sizes, int n_in,
                              void* d_out, int out_size) {
    const float* src   = (const float*)d_in[0];
    const float* grid1 = (const float*)d_in[1];
    const float* grid2 = (const float*)d_in[2];
    const float* w1    = (const float*)d_in[3];
    const float* b1    = (const float*)d_in[4];
    const float* w2    = (const float*)d_in[5];
    const float* b2    = (const float*)d_in[6];
    const float* w3    = (const float*)d_in[7];
    const float* b3    = (const float*)d_in[8];
    const float* w4    = (const float*)d_in[9];
    const float* b4    = (const float*)d_in[10];
    float* out = (float*)d_out;

    // Pre-pass: fp16 channel-last transpose of both grids.
    {
        const int total = 8 * 32 * 8 * 256;   // 524288, covers all segments
        transpose_grids_h<<<(total + 255) / 256, 256>>>(grid1, grid2);
    }

    const int total = 8 * IMG_H * IMG_W;
    bgrid_fused_kernel<<<total / 256, 256>>>(src,
                                             w1, b1, w2, b2, w3, b3, w4, b4,
                                             out);
}

// round 9
// speedup vs baseline: 2.3693x; 1.1847x over previous
#include <cuda_runtime.h>
#include <cuda_fp16.h>

#define IMG_H 512
#define IMG_W 512
#define HW (IMG_H * IMG_W)

// Channel-last fp16 staging: [b][z][y][x][32]  (1 MB each)
__device__ __half g1h[8 * 8 * 16 * 16 * 32];
__device__ __half g2h[8 * 8 * 16 * 16 * 32];   // 27 real channels + 5 zero pad

__global__ __launch_bounds__(256) void transpose_grids_h(
    const float* __restrict__ g1, const float* __restrict__ g2)
{
    const int i = blockIdx.x * 256 + threadIdx.x;
    if (i < 8 * 32 * 8 * 256) {
        const int x = i & 15, y = (i >> 4) & 15, z = (i >> 8) & 7;
        const int c = (i >> 11) & 31, b = i >> 16;
        g1h[(((b * 8 + z) * 16 + y) * 16 + x) * 32 + c] = __float2half(g1[i]);
    }
    if (i < 8 * 27 * 8 * 256) {
        const int x = i & 15, y = (i >> 4) & 15, z = (i >> 8) & 7;
        const int t = i >> 11;
        const int c = t % 27, b = t / 27;
        g2h[(((b * 8 + z) * 16 + y) * 16 + x) * 32 + c] = __float2half(g2[i]);
    }
    if (i < 8 * 8 * 256) {
#pragma unroll
        for (int c = 27; c < 32; c++) g2h[i * 32 + c] = __float2half(0.0f);
    }
}

__device__ __forceinline__ float tanh_approx(float x) {
    float y;
    asm("tanh.approx.f32 %0, %1;" : "=f"(y) : "f"(x));
    return y;
}
// ---- packed f32x2 helpers ----
typedef unsigned long long u64;
__device__ __forceinline__ u64 pk2(float lo, float hi) {
    u64 r;
    asm("mov.b64 %0, {%1, %2};" : "=l"(r) : "f"(lo), "f"(hi));
    return r;
}
__device__ __forceinline__ void upk2(float& lo, float& hi, u64 p) {
    asm("mov.b64 {%0, %1}, %2;" : "=f"(lo), "=f"(hi) : "l"(p));
}
__device__ __forceinline__ u64 fma2q(u64 a, u64 b, u64 c) {
    u64 d;
    asm("fma.rn.f32x2 %0, %1, %2, %3;" : "=l"(d) : "l"(a), "l"(b), "l"(c));
    return d;
}
// half2 -> packed f32x2 in one b64 (2x F2F; pack mov elided by regalloc)
__device__ __forceinline__ u64 h2f2(__half2 h) {
    u64 r;
    unsigned int u = *(unsigned int*)&h;
    asm("{\n\t.reg .b16 l, h;\n\t.reg .f32 fl, fh;\n\t"
        "mov.b32 {l, h}, %1;\n\t"
        "cvt.f32.f16 fl, l;\n\t"
        "cvt.f32.f16 fh, h;\n\t"
        "mov.b64 %0, {fl, fh};\n\t}" : "=l"(r) : "r"(u));
    return r;
}
__device__ __forceinline__ __half2 u2h(unsigned int u) { return *(__half2*)&u; }
__device__ __forceinline__ __half2 lerp2(__half2 a, __half2 b, __half2 w) {
    return __hfma2(w, __hsub2(b, a), a);
}

__global__ __launch_bounds__(256, 4) void bgrid_fused_kernel(
    const float* __restrict__ src,
    const float* __restrict__ w1, const float* __restrict__ b1,
    const float* __restrict__ w2, const float* __restrict__ b2,
    const float* __restrict__ w3, const float* __restrict__ b3,
    const float* __restrict__ w4, const float* __restrict__ b4,
    float* __restrict__ out)
{
    // pre-paired weights (lane pairs = output-neuron pairs)
    __shared__ float2 sp1[8][3];   // guide1: (w1[2op][j], w1[2op+1][j])
    __shared__ float2 b1p[8];
    __shared__ float  sw2[16];
    __shared__ float2 sp3[8][8];   // guide2: (w3[2op][q], w3[2op+1][q])
    __shared__ float2 b3p[8];
    __shared__ float  sw4[16];
    __shared__ float  sb2s, sb4s;

    const int tid = threadIdx.x;
    if (tid < 24) {
        const int op = tid / 3, jj = tid - op * 3;
        sp1[op][jj] = make_float2(w1[(2 * op) * 3 + jj], w1[(2 * op + 1) * 3 + jj]);
    }
    if (tid < 8) {
        b1p[tid] = make_float2(b1[2 * tid], b1[2 * tid + 1]);
        b3p[tid] = make_float2(b3[2 * tid], b3[2 * tid + 1]);
    }
    if (tid < 16) { sw2[tid] = w2[tid]; sw4[tid] = w4[tid]; }
    if (tid < 64) {
        const int op = tid >> 3, q = tid & 7;
        sp3[op][q] = make_float2(w3[(2 * op) * 8 + q], w3[(2 * op + 1) * 8 + q]);
    }
    if (tid == 0) { sb2s = b2[0]; sb4s = b4[0]; }
    __syncthreads();

    const int idx = blockIdx.x * 256 + tid;
    const int px = idx & 511;
    const int py = (idx >> 9) & 511;
    const int pb = idx >> 18;

    // ---- src pixel ----
    const float* srcp = src + (pb * 3) * HW + py * IMG_W + px;
    const float s0 = srcp[0];
    const float s1 = srcp[HW];
    const float s2 = srcp[2 * HW];
    const u64 sap[4] = {pk2(s0, s0), pk2(s1, s1), pk2(s2, s2), pk2(1.0f, 1.0f)};

    // ---- guide NN #1 (packed o-pairs) ----
    float g = sb2s;
#pragma unroll
    for (int op = 0; op < 8; op++) {
        u64 t2 = *(const u64*)&b1p[op];
        t2 = fma2q(sap[0], *(const u64*)&sp1[op][0], t2);
        t2 = fma2q(sap[1], *(const u64*)&sp1[op][1], t2);
        t2 = fma2q(sap[2], *(const u64*)&sp1[op][2], t2);
        float lo, hi; upk2(lo, hi, t2);
        lo = fmaxf(lo, 0.0f); hi = fmaxf(hi, 0.0f);
        g = fmaf(sw2[2 * op], lo, g);
        g = fmaf(sw2[2 * op + 1], hi, g);
    }
    g = tanh_approx(g);

    // ---- xy lattice ----
    const float fx = (float)px * (15.0f / 512.0f);
    const float fy = (float)py * (15.0f / 512.0f);
    const int x0 = (int)fx;
    const int y0 = (int)fy;
    const float wx = fx - (float)x0;
    const float wy = fy - (float)y0;
    const __half2 wxh = __float2half2_rn(wx);
    const __half2 wyh = __float2half2_rn(wy);
    int obase[2][2];
#pragma unroll
    for (int yi = 0; yi < 2; yi++)
#pragma unroll
        for (int xi = 0; xi < 2; xi++)
            obase[yi][xi] = ((y0 + yi) * 16 + (x0 + xi)) * 32;

    // ---- z for slice 1 ----
    float fz = fminf(fmaxf((g + 1.0f) * 3.5f, 0.0f), 7.0f);
    int z0 = (int)fz;
    if (z0 > 7) z0 = 7;
    int z1 = min(z0 + 1, 7);
    __half2 wzh = __float2half2_rn(fz - (float)z0);

    // ---- slice grid1: fp16 trilerp tree, fold into hidp[4] f32x2 packs ----
    u64 hidp[4];
#pragma unroll
    for (int e = 0; e < 4; e++) hidp[e] = pk2(0.0f, 0.0f);
    {
        const __half* gb = g1h + pb * 65536;
        const int zoff0 = z0 * 8192, zoff1 = z1 * 8192;
#pragma unroll
        for (int j = 0; j < 4; j++) {      // 8 channels per j, a = j
            __half2 zl[2][2][4];
#pragma unroll
            for (int yi = 0; yi < 2; yi++) {
#pragma unroll
                for (int xi = 0; xi < 2; xi++) {
                    const uint4 a = __ldg((const uint4*)(gb + obase[yi][xi] + zoff0) + j);
                    const uint4 b = __ldg((const uint4*)(gb + obase[yi][xi] + zoff1) + j);
                    zl[yi][xi][0] = lerp2(u2h(a.x), u2h(b.x), wzh);
                    zl[yi][xi][1] = lerp2(u2h(a.y), u2h(b.y), wzh);
                    zl[yi][xi][2] = lerp2(u2h(a.z), u2h(b.z), wzh);
                    zl[yi][xi][3] = lerp2(u2h(a.w), u2h(b.w), wzh);
                }
            }
#pragma unroll
            for (int e = 0; e < 4; e++) {
                const __half2 t0 = lerp2(zl[0][0][e], zl[0][1][e], wxh);
                const __half2 t1 = lerp2(zl[1][0][e], zl[1][1][e], wxh);
                const __half2 d  = lerp2(t0, t1, wyh);
                hidp[e] = fma2q(h2f2(d), sap[j], hidp[e]);
            }
        }
    }
    float hid[8];
#pragma unroll
    for (int e = 0; e < 4; e++) {
        float lo, hi; upk2(lo, hi, hidp[e]);
        hid[2 * e]     = fmaxf(lo, 0.0f);
        hid[2 * e + 1] = fmaxf(hi, 0.0f);
    }

    // ---- guide NN #2 (packed o-pairs) ----
    u64 hd[8];
#pragma unroll
    for (int q = 0; q < 8; q++) hd[q] = pk2(hid[q], hid[q]);
    float g2a = sb4s;
#pragma unroll
    for (int op = 0; op < 8; op++) {
        u64 t2 = *(const u64*)&b3p[op];
#pragma unroll
        for (int q = 0; q < 8; q++)
            t2 = fma2q(hd[q], *(const u64*)&sp3[op][q], t2);
        float lo, hi; upk2(lo, hi, t2);
        lo = fmaxf(lo, 0.0f); hi = fmaxf(hi, 0.0f);
        g2a = fmaf(sw4[2 * op], lo, g2a);
        g2a = fmaf(sw4[2 * op + 1], hi, g2a);
    }
    g2a = tanh_approx(g2a);

    // ---- z for slice 2 ----
    fz = fminf(fmaxf((g2a + 1.0f) * 3.5f, 0.0f), 7.0f);
    z0 = (int)fz;
    if (z0 > 7) z0 = 7;
    z1 = min(z0 + 1, 7);
    wzh = __float2half2_rn(fz - (float)z0);

    // ---- slice grid2: fp16 trilerp tree, fold into out[3] ----
    float m2[11];
#pragma unroll
    for (int q = 0; q < 8; q++) m2[q] = hid[q];
    m2[8] = 1.0f; m2[9] = 0.0f; m2[10] = 0.0f;

    float r[3] = {0.0f, 0.0f, 0.0f};
    {
        const __half* gb = g2h + pb * 65536;
        const int zoff0 = z0 * 8192, zoff1 = z1 * 8192;
#pragma unroll
        for (int j = 0; j < 4; j++) {
            __half2 zl[2][2][4];
#pragma unroll
            for (int yi = 0; yi < 2; yi++) {
#pragma unroll
                for (int xi = 0; xi < 2; xi++) {
                    const uint4 a = __ldg((const uint4*)(gb + obase[yi][xi] + zoff0) + j);
                    const uint4 b = __ldg((const uint4*)(gb + obase[yi][xi] + zoff1) + j);
                    zl[yi][xi][0] = lerp2(u2h(a.x), u2h(b.x), wzh);
                    zl[yi][xi][1] = lerp2(u2h(a.y), u2h(b.y), wzh);
                    zl[yi][xi][2] = lerp2(u2h(a.z), u2h(b.z), wzh);
                    zl[yi][xi][3] = lerp2(u2h(a.w), u2h(b.w), wzh);
                }
            }
#pragma unroll
            for (int e = 0; e < 4; e++) {
                const __half2 t0 = lerp2(zl[0][0][e], zl[0][1][e], wxh);
                const __half2 t1 = lerp2(zl[1][0][e], zl[1][1][e], wxh);
                const __half2 d  = lerp2(t0, t1, wyh);
                float lo, hi; upk2(lo, hi, h2f2(d));
                const int c = 8 * j + 2 * e;             // compile-time
                r[c % 3]       = fmaf(lo, m2[c / 3], r[c % 3]);
                r[(c + 1) % 3] = fmaf(hi, m2[(c + 1) / 3], r[(c + 1) % 3]);
            }
        }
    }

    float* outp = out + (pb * 3) * HW + py * IMG_W + px;
    outp[0]      = r[0];
    outp[HW]     = r[1];
    outp[2 * HW] = r[2];
}

extern "C" void kernel_launch(void* const* d_in, const int* in_sizes, int n_in,
                              void* d_out, int out_size) {
    const float* src   = (const float*)d_in[0];
    const float* grid1 = (const float*)d_in[1];
    const float* grid2 = (const float*)d_in[2];
    const float* w1    = (const float*)d_in[3];
    const float* b1    = (const float*)d_in[4];
    const float* w2    = (const float*)d_in[5];
    const float* b2    = (const float*)d_in[6];
    const float* w3    = (const float*)d_in[7];
    const float* b3    = (const float*)d_in[8];
    const float* w4    = (const float*)d_in[9];
    const float* b4    = (const float*)d_in[10];
    float* out = (float*)d_out;

    {
        const int total = 8 * 32 * 8 * 256;
        transpose_grids_h<<<(total + 255) / 256, 256>>>(grid1, grid2);
    }
    const int total = 8 * IMG_H * IMG_W;
    bgrid_fused_kernel<<<total / 256, 256>>>(src,
                                             w1, b1, w2, b2, w3, b3, w4, b4,
                                             out);
}